// round 4
// baseline (speedup 1.0000x reference)
#include <cuda_runtime.h>
#include <cstdint>

__device__ __forceinline__ float sigm(float x) { return 1.0f / (1.0f + __expf(-x)); }

// Slot layout for u/v exchange: slot s = g*8 + phase (0..31 per warp's worth),
// address = s*21 + c. 21 is coprime to 32 -> the 32 slots hit 32 distinct banks
// at any fixed c: conflict-free STS; LDS reads are broadcast or distinct.
#define SLOT_STRIDE 21

// Small live set (~55 regs true): u lives in shared, j-loop keeps only comb[20].
// 5 blocks/SM -> 102-reg cap, 20 warps/SM (31% occ).
__global__ __launch_bounds__(128, 5)
void frap_kernel(const float* __restrict__ states,
                 const int*   __restrict__ comp_mask,
                 const int*   __restrict__ phase_pairs,
                 const float* __restrict__ p_w,
                 const float* __restrict__ d_w,  const float* __restrict__ d_b,
                 const float* __restrict__ le_w, const float* __restrict__ le_b,
                 const float* __restrict__ lc_w, const float* __restrict__ lc_b,
                 const float* __restrict__ rel_w,
                 const float* __restrict__ rc_w, const float* __restrict__ rc_b,
                 const float* __restrict__ h_w,  const float* __restrict__ h_b,
                 const float* __restrict__ bm_w, const float* __restrict__ bm_b,
                 float* __restrict__ out, int B)
{
    __shared__ float s_lcA[20][16];         // lc_w[:, 0:16]
    __shared__ float s_lcB[20][16];         // lc_w[:, 16:32]
    __shared__ __align__(16) float s_hw[20][20];   // rows 80B (16B-aligned) -> float4 broadcast
    __shared__ float s_rel[56][20];         // relu(relu(rel_w[comp_mask]) @ rc_w^T + rc_b)
    __shared__ float s_leD[4][16];          // le_w[4:8, :]
    __shared__ float s_lcb[20], s_hb[20], s_bmw[20], s_dw[4], s_db[4];
    __shared__ float s_base[2][16];         // le_b + sigmoid(p_w[e]) @ le_w[0:4, :]
    __shared__ int   s_pp[16];
    __shared__ float s_bmb;
    __shared__ float s_u[128 * SLOT_STRIDE];   // u per (g, i) slot
    __shared__ float s_v[128 * SLOT_STRIDE];   // v per (g, j) slot

    const int tid = threadIdx.x;

    // ---------------- block-local precompute (batch-independent, tiny) ----------------
    for (int idx = tid; idx < 320; idx += 128) {
        int o = idx >> 4, c = idx & 15;
        s_lcA[o][c] = lc_w[o * 32 + c];
        s_lcB[o][c] = lc_w[o * 32 + 16 + c];
    }
    for (int idx = tid; idx < 400; idx += 128) {
        int o = idx / 20, c = idx % 20;
        s_hw[o][c] = h_w[o * 20 + c];
    }
    for (int idx = tid; idx < 1120; idx += 128) {
        int pq = idx / 20, o = idx % 20;
        int e = comp_mask[pq];              // [8][7] row-major, in {0,1}
        float acc = rc_b[o];
        #pragma unroll
        for (int c4 = 0; c4 < 4; c4++)
            acc += fmaxf(rel_w[e * 4 + c4], 0.0f) * rc_w[o * 4 + c4];
        s_rel[pq][o] = fmaxf(acc, 0.0f);
    }
    for (int idx = tid; idx < 64; idx += 128) {
        int k = idx >> 4, c = idx & 15;
        s_leD[k][c] = le_w[(4 + k) * 16 + c];
    }
    if (tid < 32) {
        int e = tid >> 4, c = tid & 15;
        float a = le_b[c];
        #pragma unroll
        for (int k = 0; k < 4; k++) a += sigm(p_w[e * 4 + k]) * le_w[k * 16 + c];
        s_base[e][c] = a;
    }
    if (tid < 20) {
        s_lcb[tid] = lc_b[tid];
        s_hb[tid]  = h_b[tid];
        s_bmw[tid] = bm_w[tid];
    }
    if (tid < 4) { s_dw[tid] = d_w[tid]; s_db[tid] = d_b[tid]; }
    if (tid < 16) s_pp[tid] = phase_pairs[tid];
    if (tid == 0) s_bmb = bm_b[0];
    __syncthreads();

    // ---------------- per-thread: (batch elem b) x (output phase i) ----------------
    const int g = tid >> 3;                 // 0..15: batch elem within block
    const int i = tid & 7;                  // output phase
    const int b = blockIdx.x * 16 + g;
    const bool valid = (b < B);
    const float* st = states + (valid ? b : 0) * 13;

    const int a  = (int)st[0];
    const int pa0 = s_pp[a * 2], pa1 = s_pp[a * 2 + 1];
    const int mA  = s_pp[i * 2], mB  = s_pp[i * 2 + 1];

    // pairs[i] = lane[mA] + lane[mB]
    float pairs[16];
    #pragma unroll
    for (int c = 0; c < 16; c++) pairs[c] = 0.0f;

    #pragma unroll
    for (int t = 0; t < 2; t++) {
        const int m = (t == 0) ? mA : mB;
        const float dm = st[1 + m];
        float de[4];
        #pragma unroll
        for (int k = 0; k < 4; k++) de[k] = sigm(fmaf(dm, s_dw[k], s_db[k]));
        const int e = (m == pa0 || m == pa1) ? 1 : 0;
        #pragma unroll
        for (int c = 0; c < 16; c++) {
            float acc = s_base[e][c];
            #pragma unroll
            for (int k = 0; k < 4; k++) acc = fmaf(de[k], s_leD[k][c], acc);
            pairs[c] += fmaxf(acc, 0.0f);
        }
    }

    // u = lcA @ pairs + lc_b; v = lcB @ pairs  -> both straight to shared (no reg arrays)
    const int slot = (g * 8 + i) * SLOT_STRIDE;
    #pragma unroll
    for (int o = 0; o < 20; o++) {
        float au = s_lcb[o];
        float av = 0.0f;
        #pragma unroll
        for (int c = 0; c < 16; c++) {
            au = fmaf(s_lcA[o][c], pairs[c], au);
            av = fmaf(s_lcB[o][c], pairs[c], av);
        }
        s_u[slot + o] = au;
        s_v[slot + o] = av;
    }
    __syncthreads();

    // j-loop: comb = relu(u + v_j) * rel[i][q]; h = relu(h_w@comb + h_b); acc += bm_w . h
    const float* my_u = &s_u[slot];
    float acc = 0.0f;
    #pragma unroll 1
    for (int q = 0; q < 7; q++) {
        const int j = q + (q >= i ? 1 : 0);
        const float* vj = &s_v[(g * 8 + j) * SLOT_STRIDE];
        const float* rl = &s_rel[i * 7 + q][0];
        float comb[20];
        #pragma unroll
        for (int c = 0; c < 20; c++)
            comb[c] = fmaxf(my_u[c] + vj[c], 0.0f) * rl[c];
        #pragma unroll
        for (int o = 0; o < 20; o++) {
            const float4* hw4 = reinterpret_cast<const float4*>(&s_hw[o][0]);
            float h = s_hb[o];
            #pragma unroll
            for (int c4 = 0; c4 < 5; c4++) {
                float4 w = hw4[c4];
                h = fmaf(w.x, comb[c4 * 4 + 0], h);
                h = fmaf(w.y, comb[c4 * 4 + 1], h);
                h = fmaf(w.z, comb[c4 * 4 + 2], h);
                h = fmaf(w.w, comb[c4 * 4 + 3], h);
            }
            acc = fmaf(s_bmw[o], fmaxf(h, 0.0f), acc);
        }
    }

    if (valid) out[b * 8 + i] = acc + 7.0f * s_bmb;   // coalesced: base*8 + tid
}

extern "C" void kernel_launch(void* const* d_in, const int* in_sizes, int n_in,
                              void* d_out, int out_size)
{
    const float* states      = (const float*)d_in[0];
    const int*   comp_mask   = (const int*)  d_in[1];
    const int*   phase_pairs = (const int*)  d_in[2];
    const float* p_w  = (const float*)d_in[3];
    const float* d_w  = (const float*)d_in[4];
    const float* d_b  = (const float*)d_in[5];
    const float* le_w = (const float*)d_in[6];
    const float* le_b = (const float*)d_in[7];
    const float* lc_w = (const float*)d_in[8];
    const float* lc_b = (const float*)d_in[9];
    const float* rel_w = (const float*)d_in[10];
    const float* rc_w  = (const float*)d_in[11];
    const float* rc_b  = (const float*)d_in[12];
    const float* h_w   = (const float*)d_in[13];
    const float* h_b   = (const float*)d_in[14];
    const float* bm_w  = (const float*)d_in[15];
    const float* bm_b  = (const float*)d_in[16];

    const int B = in_sizes[0] / 13;           // states is [B, 1 + 12]
    const int blocks = (B + 15) / 16;         // 16 batch elems x 8 phases per 128-thread block

    frap_kernel<<<blocks, 128>>>(states, comp_mask, phase_pairs,
                                 p_w, d_w, d_b, le_w, le_b, lc_w, lc_b,
                                 rel_w, rc_w, rc_b, h_w, h_b, bm_w, bm_b,
                                 (float*)d_out, B);
}

// round 5
// speedup vs baseline: 5.8859x; 5.8859x over previous
#include <cuda_runtime.h>
#include <cstdint>

__device__ __forceinline__ float sigm(float x) { return 1.0f / (1.0f + __expf(-x)); }

// u/v exchange: slot = tid (= g*8 + i), stride 20 floats (80B, 16B-aligned).
// float4 accesses: group index = slot*5 + c4; 5 coprime 8 -> conflict-free
// (exactly the 128B/wavefront floor, no replays).

__global__ __launch_bounds__(128, 4)
void frap_kernel(const float* __restrict__ states,
                 const int*   __restrict__ comp_mask,
                 const int*   __restrict__ phase_pairs,
                 const float* __restrict__ p_w,
                 const float* __restrict__ d_w,  const float* __restrict__ d_b,
                 const float* __restrict__ le_w, const float* __restrict__ le_b,
                 const float* __restrict__ lc_w, const float* __restrict__ lc_b,
                 const float* __restrict__ rel_w,
                 const float* __restrict__ rc_w, const float* __restrict__ rc_b,
                 const float* __restrict__ h_w,  const float* __restrict__ h_b,
                 const float* __restrict__ bm_w, const float* __restrict__ bm_b,
                 float* __restrict__ out, int B)
{
    __shared__ __align__(16) float s_lcA[20][16];   // lc_w[:, 0:16]  (64B rows)
    __shared__ __align__(16) float s_lcB[20][16];   // lc_w[:, 16:32]
    __shared__ __align__(16) float s_hw[20][20];    // 80B rows -> float4
    __shared__ __align__(16) float s_rel[56][20];   // precomputed rel stage, 80B rows
    __shared__ float s_leD[4][16];                  // le_w[4:8, :]
    __shared__ float s_lcb[20], s_hb[20], s_bmw[20], s_dw[4], s_db[4];
    __shared__ float s_base[2][16];                 // le_b + sigmoid(p_w[e]) @ le_w[0:4,:]
    __shared__ int   s_pp[16];
    __shared__ float s_bmb;
    __shared__ __align__(16) float s_u[128 * 20];   // u per (g,i) slot
    __shared__ __align__(16) float s_v[128 * 20];   // v per (g,j) slot

    const int tid = threadIdx.x;

    // ---------------- block-local precompute (batch-independent, tiny) ----------------
    for (int idx = tid; idx < 320; idx += 128) {
        int o = idx >> 4, c = idx & 15;
        s_lcA[o][c] = lc_w[o * 32 + c];
        s_lcB[o][c] = lc_w[o * 32 + 16 + c];
    }
    for (int idx = tid; idx < 400; idx += 128) {
        int o = idx / 20, c = idx % 20;
        s_hw[o][c] = h_w[o * 20 + c];
    }
    for (int idx = tid; idx < 1120; idx += 128) {
        int pq = idx / 20, o = idx % 20;
        int e = comp_mask[pq];
        float acc = rc_b[o];
        #pragma unroll
        for (int c4 = 0; c4 < 4; c4++)
            acc += fmaxf(rel_w[e * 4 + c4], 0.0f) * rc_w[o * 4 + c4];
        s_rel[pq][o] = fmaxf(acc, 0.0f);
    }
    for (int idx = tid; idx < 64; idx += 128) {
        int k = idx >> 4, c = idx & 15;
        s_leD[k][c] = le_w[(4 + k) * 16 + c];
    }
    if (tid < 32) {
        int e = tid >> 4, c = tid & 15;
        float a = le_b[c];
        #pragma unroll
        for (int k = 0; k < 4; k++) a += sigm(p_w[e * 4 + k]) * le_w[k * 16 + c];
        s_base[e][c] = a;
    }
    if (tid < 20) {
        s_lcb[tid] = lc_b[tid];
        s_hb[tid]  = h_b[tid];
        s_bmw[tid] = bm_w[tid];
    }
    if (tid < 4) { s_dw[tid] = d_w[tid]; s_db[tid] = d_b[tid]; }
    if (tid < 16) s_pp[tid] = phase_pairs[tid];
    if (tid == 0) s_bmb = bm_b[0];
    __syncthreads();

    // ---------------- per-thread: (batch elem b) x (output phase i) ----------------
    const int g = tid >> 3;
    const int i = tid & 7;
    const int b = blockIdx.x * 16 + g;
    const bool valid = (b < B);
    const float* st = states + (valid ? b : 0) * 13;

    const int a  = (int)st[0];
    const int pa0 = s_pp[a * 2], pa1 = s_pp[a * 2 + 1];
    const int mA  = s_pp[i * 2], mB  = s_pp[i * 2 + 1];

    // ---------- stage 0: pairs[i] = lane[mA] + lane[mB] ----------
    float pairs[16];
    #pragma unroll
    for (int c = 0; c < 16; c++) pairs[c] = 0.0f;

    #pragma unroll
    for (int t = 0; t < 2; t++) {
        const int m = (t == 0) ? mA : mB;
        const float dm = st[1 + m];
        float de[4];
        #pragma unroll
        for (int k = 0; k < 4; k++) de[k] = sigm(fmaf(dm, s_dw[k], s_db[k]));
        const int e = (m == pa0 || m == pa1) ? 1 : 0;
        #pragma unroll
        for (int c = 0; c < 16; c++) {
            float acc = s_base[e][c];
            #pragma unroll
            for (int k = 0; k < 4; k++) acc = fmaf(de[k], s_leD[k][c], acc);
            pairs[c] += fmaxf(acc, 0.0f);
        }
    }

    // ---------- stage 1: u = lcA@pairs + lc_b; v = lcB@pairs -> shared (float4 packed) ----------
    {
        float4* u4p = reinterpret_cast<float4*>(&s_u[tid * 20]);
        float4* v4p = reinterpret_cast<float4*>(&s_v[tid * 20]);
        #pragma unroll 1
        for (int ob = 0; ob < 5; ob++) {
            float ur[4], vr[4];
            #pragma unroll
            for (int oi = 0; oi < 4; oi++) {
                const int o = ob * 4 + oi;
                const float4* wa = reinterpret_cast<const float4*>(&s_lcA[o][0]);
                const float4* wb = reinterpret_cast<const float4*>(&s_lcB[o][0]);
                float au = s_lcb[o], av = 0.0f;
                #pragma unroll
                for (int c4 = 0; c4 < 4; c4++) {
                    float4 A = wa[c4], Bv = wb[c4];
                    au = fmaf(A.x,  pairs[c4 * 4 + 0], au);
                    av = fmaf(Bv.x, pairs[c4 * 4 + 0], av);
                    au = fmaf(A.y,  pairs[c4 * 4 + 1], au);
                    av = fmaf(Bv.y, pairs[c4 * 4 + 1], av);
                    au = fmaf(A.z,  pairs[c4 * 4 + 2], au);
                    av = fmaf(Bv.z, pairs[c4 * 4 + 2], av);
                    au = fmaf(A.w,  pairs[c4 * 4 + 3], au);
                    av = fmaf(Bv.w, pairs[c4 * 4 + 3], av);
                }
                ur[oi] = au; vr[oi] = av;
            }
            u4p[ob] = make_float4(ur[0], ur[1], ur[2], ur[3]);
            v4p[ob] = make_float4(vr[0], vr[1], vr[2], vr[3]);
        }
    }
    __syncthreads();

    // ---------- stage 2 (j-loop): comb = relu(u+v_j)*rel; h = relu(hw@comb+hb); acc += bmw.h ----------
    const float4* myu = reinterpret_cast<const float4*>(&s_u[tid * 20]);
    const int gbase = (tid - i) * 20;          // (g*8)*20
    float acc = 0.0f;

    #pragma unroll 1
    for (int q = 0; q < 7; q++) {
        const int j = q + (q >= i ? 1 : 0);
        const float4* vj = reinterpret_cast<const float4*>(&s_v[gbase + j * 20]);
        const float4* rl = reinterpret_cast<const float4*>(&s_rel[i * 7 + q][0]);

        float comb[20];
        #pragma unroll
        for (int c4 = 0; c4 < 5; c4++) {
            float4 uu = myu[c4], vv = vj[c4], rr = rl[c4];
            comb[c4 * 4 + 0] = fmaxf(uu.x + vv.x, 0.0f) * rr.x;
            comb[c4 * 4 + 1] = fmaxf(uu.y + vv.y, 0.0f) * rr.y;
            comb[c4 * 4 + 2] = fmaxf(uu.z + vv.z, 0.0f) * rr.z;
            comb[c4 * 4 + 3] = fmaxf(uu.w + vv.w, 0.0f) * rr.w;
        }

        #pragma unroll 2
        for (int o = 0; o < 20; o++) {
            const float4* hw4 = reinterpret_cast<const float4*>(&s_hw[o][0]);
            float h = s_hb[o];
            #pragma unroll
            for (int c4 = 0; c4 < 5; c4++) {
                float4 w = hw4[c4];
                h = fmaf(w.x, comb[c4 * 4 + 0], h);
                h = fmaf(w.y, comb[c4 * 4 + 1], h);
                h = fmaf(w.z, comb[c4 * 4 + 2], h);
                h = fmaf(w.w, comb[c4 * 4 + 3], h);
            }
            acc = fmaf(s_bmw[o], fmaxf(h, 0.0f), acc);
        }
    }

    if (valid) out[b * 8 + i] = acc + 7.0f * s_bmb;   // coalesced: base*8 + tid
}

extern "C" void kernel_launch(void* const* d_in, const int* in_sizes, int n_in,
                              void* d_out, int out_size)
{
    const float* states      = (const float*)d_in[0];
    const int*   comp_mask   = (const int*)  d_in[1];
    const int*   phase_pairs = (const int*)  d_in[2];
    const float* p_w  = (const float*)d_in[3];
    const float* d_w  = (const float*)d_in[4];
    const float* d_b  = (const float*)d_in[5];
    const float* le_w = (const float*)d_in[6];
    const float* le_b = (const float*)d_in[7];
    const float* lc_w = (const float*)d_in[8];
    const float* lc_b = (const float*)d_in[9];
    const float* rel_w = (const float*)d_in[10];
    const float* rc_w  = (const float*)d_in[11];
    const float* rc_b  = (const float*)d_in[12];
    const float* h_w   = (const float*)d_in[13];
    const float* h_b   = (const float*)d_in[14];
    const float* bm_w  = (const float*)d_in[15];
    const float* bm_b  = (const float*)d_in[16];

    const int B = in_sizes[0] / 13;           // states is [B, 1 + 12]
    const int blocks = (B + 15) / 16;         // 16 batch elems x 8 phases per 128-thread block

    frap_kernel<<<blocks, 128>>>(states, comp_mask, phase_pairs,
                                 p_w, d_w, d_b, le_w, le_b, lc_w, lc_b,
                                 rel_w, rc_w, rc_b, h_w, h_b, bm_w, bm_b,
                                 (float*)d_out, B);
}

// round 6
// speedup vs baseline: 6.2361x; 1.0595x over previous
#include <cuda_runtime.h>
#include <cstdint>

__device__ __forceinline__ float sigm(float x) { return 1.0f / (1.0f + __expf(-x)); }

// u/v exchange layout: addr = g*168 + phase*20 + c  (floats).
// 168*4B = 672B (16B-aligned); 168 mod 32 = 8 -> the 4 per-warp g-bases hit
// bank groups 0/8/16/24 -> vj LDS128 (4 unique addrs) = 1 wavefront.
#define G_STRIDE 168

__global__ __launch_bounds__(128, 4)
void frap_kernel(const float* __restrict__ states,
                 const int*   __restrict__ comp_mask,
                 const int*   __restrict__ phase_pairs,
                 const float* __restrict__ p_w,
                 const float* __restrict__ d_w,  const float* __restrict__ d_b,
                 const float* __restrict__ le_w, const float* __restrict__ le_b,
                 const float* __restrict__ lc_w, const float* __restrict__ lc_b,
                 const float* __restrict__ rel_w,
                 const float* __restrict__ rc_w, const float* __restrict__ rc_b,
                 const float* __restrict__ h_w,  const float* __restrict__ h_b,
                 const float* __restrict__ bm_w, const float* __restrict__ bm_b,
                 float* __restrict__ out, int B)
{
    __shared__ __align__(16) float s_lcA[20][16];   // lc_w[:, 0:16]
    __shared__ __align__(16) float s_lcB[20][16];   // lc_w[:, 16:32]
    __shared__ __align__(16) float s_hw[20][20];    // 80B rows -> float4 broadcast
    __shared__ __align__(16) float s_rel[8 * 8 * 20]; // [q][i][20]; zero row when q==i
    __shared__ float s_leD[4][16];
    __shared__ float s_lcb[20], s_hb[20], s_bmw[20], s_dw[4], s_db[4];
    __shared__ float s_base[2][16];
    __shared__ int   s_pp[16];
    __shared__ float s_bmb, s_corr;                 // corr = sum_o bm[o]*relu(h_b[o])
    __shared__ __align__(16) float s_u[16 * G_STRIDE];
    __shared__ __align__(16) float s_v[16 * G_STRIDE];

    const int tid = threadIdx.x;

    // ---------------- block-local precompute ----------------
    for (int idx = tid; idx < 320; idx += 128) {
        int o = idx >> 4, c = idx & 15;
        s_lcA[o][c] = lc_w[o * 32 + c];
        s_lcB[o][c] = lc_w[o * 32 + 16 + c];
    }
    for (int idx = tid; idx < 400; idx += 128) {
        int o = idx / 20, c = idx % 20;
        s_hw[o][c] = h_w[o * 20 + c];
    }
    // s_rel[q][i][o]: pair (i, j=q). q==i -> 0 (dummy lane, corrected via s_corr).
    for (int idx = tid; idx < 1280; idx += 128) {
        int qi = idx / 20, o = idx % 20;
        int q = qi >> 3, i = qi & 7;
        float val = 0.0f;
        if (q != i) {
            int cm = i * 7 + (q > i ? q - 1 : q);
            int e = comp_mask[cm];
            float acc = rc_b[o];
            #pragma unroll
            for (int c4 = 0; c4 < 4; c4++)
                acc += fmaxf(rel_w[e * 4 + c4], 0.0f) * rc_w[o * 4 + c4];
            val = fmaxf(acc, 0.0f);
        }
        s_rel[qi * 20 + o] = val;
    }
    for (int idx = tid; idx < 64; idx += 128) {
        int k = idx >> 4, c = idx & 15;
        s_leD[k][c] = le_w[(4 + k) * 16 + c];
    }
    if (tid < 32) {
        int e = tid >> 4, c = tid & 15;
        float a = le_b[c];
        #pragma unroll
        for (int k = 0; k < 4; k++) a += sigm(p_w[e * 4 + k]) * le_w[k * 16 + c];
        s_base[e][c] = a;
    }
    if (tid < 20) {
        s_lcb[tid] = lc_b[tid];
        s_hb[tid]  = h_b[tid];
        s_bmw[tid] = bm_w[tid];
    }
    if (tid < 4) { s_dw[tid] = d_w[tid]; s_db[tid] = d_b[tid]; }
    if (tid < 16) s_pp[tid] = phase_pairs[tid];
    if (tid == 0) {
        s_bmb = bm_b[0];
        float corr = 0.0f;
        #pragma unroll
        for (int o = 0; o < 20; o++) corr += bm_w[o] * fmaxf(h_b[o], 0.0f);
        s_corr = corr;
    }
    __syncthreads();

    // ---------------- per-thread: (batch elem b) x (output phase i) ----------------
    const int g = tid >> 3;
    const int i = tid & 7;
    const int b = blockIdx.x * 16 + g;
    const bool valid = (b < B);
    const float* st = states + (valid ? b : 0) * 13;

    const int a  = (int)st[0];
    const int pa0 = s_pp[a * 2], pa1 = s_pp[a * 2 + 1];
    const int mA  = s_pp[i * 2], mB  = s_pp[i * 2 + 1];

    // ---------- stage 0: pairs[i] = lane[mA] + lane[mB] ----------
    float pairs[16];
    #pragma unroll
    for (int c = 0; c < 16; c++) pairs[c] = 0.0f;

    #pragma unroll
    for (int t = 0; t < 2; t++) {
        const int m = (t == 0) ? mA : mB;
        const float dm = st[1 + m];
        float de[4];
        #pragma unroll
        for (int k = 0; k < 4; k++) de[k] = sigm(fmaf(dm, s_dw[k], s_db[k]));
        const int e = (m == pa0 || m == pa1) ? 1 : 0;
        #pragma unroll
        for (int c = 0; c < 16; c++) {
            float acc = s_base[e][c];
            #pragma unroll
            for (int k = 0; k < 4; k++) acc = fmaf(de[k], s_leD[k][c], acc);
            pairs[c] += fmaxf(acc, 0.0f);
        }
    }

    // ---------- stage 1: u = lcA@pairs + lc_b; v = lcB@pairs -> shared ----------
    const int slot = g * G_STRIDE + i * 20;
    {
        float4* u4p = reinterpret_cast<float4*>(&s_u[slot]);
        float4* v4p = reinterpret_cast<float4*>(&s_v[slot]);
        #pragma unroll 1
        for (int ob = 0; ob < 5; ob++) {
            float ur[4], vr[4];
            #pragma unroll
            for (int oi = 0; oi < 4; oi++) {
                const int o = ob * 4 + oi;
                const float4* wa = reinterpret_cast<const float4*>(&s_lcA[o][0]);
                const float4* wb = reinterpret_cast<const float4*>(&s_lcB[o][0]);
                float au = s_lcb[o], av = 0.0f;
                #pragma unroll
                for (int c4 = 0; c4 < 4; c4++) {
                    float4 A = wa[c4], Bv = wb[c4];
                    au = fmaf(A.x,  pairs[c4 * 4 + 0], au);
                    av = fmaf(Bv.x, pairs[c4 * 4 + 0], av);
                    au = fmaf(A.y,  pairs[c4 * 4 + 1], au);
                    av = fmaf(Bv.y, pairs[c4 * 4 + 1], av);
                    au = fmaf(A.z,  pairs[c4 * 4 + 2], au);
                    av = fmaf(Bv.z, pairs[c4 * 4 + 2], av);
                    au = fmaf(A.w,  pairs[c4 * 4 + 3], au);
                    av = fmaf(Bv.w, pairs[c4 * 4 + 3], av);
                }
                ur[oi] = au; vr[oi] = av;
            }
            u4p[ob] = make_float4(ur[0], ur[1], ur[2], ur[3]);
            v4p[ob] = make_float4(vr[0], vr[1], vr[2], vr[3]);
        }
    }
    __syncthreads();

    // ---------- stage 2: uniform 8-q loop, chunked by 2 (weight rows amortized) ----------
    float u[20];
    {
        const float4* up = reinterpret_cast<const float4*>(&s_u[slot]);
        #pragma unroll
        for (int c4 = 0; c4 < 5; c4++) {
            float4 t = up[c4];
            u[c4 * 4 + 0] = t.x; u[c4 * 4 + 1] = t.y;
            u[c4 * 4 + 2] = t.z; u[c4 * 4 + 3] = t.w;
        }
    }

    const int gv = g * G_STRIDE;
    float acc = 0.0f;

    #pragma unroll 1
    for (int qc = 0; qc < 4; qc++) {
        const int q0 = qc * 2, q1 = q0 + 1;
        float comb0[20], comb1[20];
        {
            const float4* v0 = reinterpret_cast<const float4*>(&s_v[gv + q0 * 20]);
            const float4* r0 = reinterpret_cast<const float4*>(&s_rel[(q0 * 8 + i) * 20]);
            const float4* v1 = reinterpret_cast<const float4*>(&s_v[gv + q1 * 20]);
            const float4* r1 = reinterpret_cast<const float4*>(&s_rel[(q1 * 8 + i) * 20]);
            #pragma unroll
            for (int c4 = 0; c4 < 5; c4++) {
                float4 vv0 = v0[c4], rr0 = r0[c4];
                float4 vv1 = v1[c4], rr1 = r1[c4];
                comb0[c4 * 4 + 0] = fmaxf(u[c4 * 4 + 0] + vv0.x, 0.0f) * rr0.x;
                comb0[c4 * 4 + 1] = fmaxf(u[c4 * 4 + 1] + vv0.y, 0.0f) * rr0.y;
                comb0[c4 * 4 + 2] = fmaxf(u[c4 * 4 + 2] + vv0.z, 0.0f) * rr0.z;
                comb0[c4 * 4 + 3] = fmaxf(u[c4 * 4 + 3] + vv0.w, 0.0f) * rr0.w;
                comb1[c4 * 4 + 0] = fmaxf(u[c4 * 4 + 0] + vv1.x, 0.0f) * rr1.x;
                comb1[c4 * 4 + 1] = fmaxf(u[c4 * 4 + 1] + vv1.y, 0.0f) * rr1.y;
                comb1[c4 * 4 + 2] = fmaxf(u[c4 * 4 + 2] + vv1.z, 0.0f) * rr1.z;
                comb1[c4 * 4 + 3] = fmaxf(u[c4 * 4 + 3] + vv1.w, 0.0f) * rr1.w;
            }
        }

        #pragma unroll 2
        for (int o = 0; o < 20; o++) {
            const float4* hw4 = reinterpret_cast<const float4*>(&s_hw[o][0]);
            float h0 = s_hb[o], h1 = h0;
            #pragma unroll
            for (int c4 = 0; c4 < 5; c4++) {
                float4 w = hw4[c4];
                h0 = fmaf(w.x, comb0[c4 * 4 + 0], h0);
                h1 = fmaf(w.x, comb1[c4 * 4 + 0], h1);
                h0 = fmaf(w.y, comb0[c4 * 4 + 1], h0);
                h1 = fmaf(w.y, comb1[c4 * 4 + 1], h1);
                h0 = fmaf(w.z, comb0[c4 * 4 + 2], h0);
                h1 = fmaf(w.z, comb1[c4 * 4 + 2], h1);
                h0 = fmaf(w.w, comb0[c4 * 4 + 3], h0);
                h1 = fmaf(w.w, comb1[c4 * 4 + 3], h1);
            }
            const float bw = s_bmw[o];
            acc = fmaf(bw, fmaxf(h0, 0.0f), acc);
            acc = fmaf(bw, fmaxf(h1, 0.0f), acc);
        }
    }

    // subtract dummy-q contribution (comb=0 -> h=h_b), add 7x bm bias
    if (valid) out[b * 8 + i] = acc - s_corr + 7.0f * s_bmb;
}

extern "C" void kernel_launch(void* const* d_in, const int* in_sizes, int n_in,
                              void* d_out, int out_size)
{
    const float* states      = (const float*)d_in[0];
    const int*   comp_mask   = (const int*)  d_in[1];
    const int*   phase_pairs = (const int*)  d_in[2];
    const float* p_w  = (const float*)d_in[3];
    const float* d_w  = (const float*)d_in[4];
    const float* d_b  = (const float*)d_in[5];
    const float* le_w = (const float*)d_in[6];
    const float* le_b = (const float*)d_in[7];
    const float* lc_w = (const float*)d_in[8];
    const float* lc_b = (const float*)d_in[9];
    const float* rel_w = (const float*)d_in[10];
    const float* rc_w  = (const float*)d_in[11];
    const float* rc_b  = (const float*)d_in[12];
    const float* h_w   = (const float*)d_in[13];
    const float* h_b   = (const float*)d_in[14];
    const float* bm_w  = (const float*)d_in[15];
    const float* bm_b  = (const float*)d_in[16];

    const int B = in_sizes[0] / 13;           // states is [B, 1 + 12]
    const int blocks = (B + 15) / 16;         // 16 batch elems x 8 phases per 128-thread block

    frap_kernel<<<blocks, 128>>>(states, comp_mask, phase_pairs,
                                 p_w, d_w, d_b, le_w, le_b, lc_w, lc_b,
                                 rel_w, rc_w, rc_b, h_w, h_b, bm_w, bm_b,
                                 (float*)d_out, B);
}